// round 1
// baseline (speedup 1.0000x reference)
#include <cuda_runtime.h>
#include <math.h>

#define IMG   512
#define NPIX  (IMG*IMG)
#define NB    4
#define NO    6
#define NL    4
#define TILE  64
#define AR    71      // TILE + 7 (window rows i-3..i+4)
#define XR    78      // TILE + 14 (double halo for prep)
#define XS    80      // X smem stride
#define H1S   72
#define ACS   72
#define H2S   65
#define HSS   65
#define EPS   1e-20f

// ---- scratch (static device globals; no allocation in kernel_launch) ----
__device__ float d_ac [NB*NO*NPIX];
__device__ float d_sii[NB*NO*NPIX];
__device__ float d_bc [NB*NL*NPIX];
__device__ float d_sjj[NB*NL*NPIX];
__device__ float d_partial[NB*NO*64];

// =========================================================================
// prep: per image compute ac = x - boxmean(x) and s = max(box(ac^2), EPS)
// grid: (8, 8, 40)  images 0..23 = outputs, 24..39 = labels
// =========================================================================
__global__ __launch_bounds__(256)
void prep_kernel(const float* __restrict__ outs, const float* __restrict__ labs) {
    extern __shared__ float sm[];
    float* X  = sm;                 // XR*XS
    float* H1 = X  + XR*XS;         // XR*H1S
    float* AC = H1 + XR*H1S;        // AR*ACS
    float* H2 = AC + AR*ACS;        // AR*H2S

    int img = blockIdx.z;
    const float* src;
    float *acg, *sg;
    if (img < NB*NO) { src = outs + (size_t)img*NPIX; acg = d_ac + (size_t)img*NPIX; sg = d_sii + (size_t)img*NPIX; }
    else { int j = img - NB*NO; src = labs + (size_t)j*NPIX; acg = d_bc + (size_t)j*NPIX; sg = d_sjj + (size_t)j*NPIX; }

    int tx0 = blockIdx.x * TILE, ty0 = blockIdx.y * TILE;
    int tid = threadIdx.x;

    // load X (78x78), zero outside image
    for (int idx = tid; idx < XR*XR; idx += 256) {
        int r = idx / XR, c = idx % XR;
        int gr = ty0 + r - 6, gc = tx0 + c - 6;
        float v = 0.f;
        if ((unsigned)gr < (unsigned)IMG && (unsigned)gc < (unsigned)IMG) v = src[gr*IMG + gc];
        X[r*XS + c] = v;
    }
    __syncthreads();

    // H1[r][c] = sum_{d=0..7} X[r][c+d], r in [0,78), c in [0,71)
    for (int idx = tid; idx < XR*4; idx += 256) {
        int r = idx >> 2, q = idx & 3;
        int c0 = q * 18;
        int cnt = min(18, AR - c0);
        const float* xr = X + r*XS + c0;
        float s = 0.f;
        #pragma unroll
        for (int d = 0; d < 8; d++) s += xr[d];
        float* hr = H1 + r*H1S + c0;
        hr[0] = s;
        for (int k = 1; k < cnt; k++) { s += xr[k+7] - xr[k-1]; hr[k] = s; }
    }
    __syncthreads();

    // V1: AC[la_r][la_c] = x - mu (0 outside image); write central 64x64 to global
    for (int idx = tid; idx < AR*4; idx += 256) {
        int g = idx / AR, c = idx % AR;
        int r0 = g * 18;
        int cnt = min(18, AR - r0);
        float s = 0.f;
        #pragma unroll
        for (int d = 0; d < 8; d++) s += H1[(r0+d)*H1S + c];
        for (int k = 0; k < cnt; k++) {
            int la_r = r0 + k;
            int gr = ty0 + la_r - 3, gc = tx0 + c - 3;
            float ac = 0.f;
            if ((unsigned)gr < (unsigned)IMG && (unsigned)gc < (unsigned)IMG)
                ac = X[(la_r+3)*XS + (c+3)] - s * (1.f/64.f);
            AC[la_r*ACS + c] = ac;
            if (la_r >= 3 && la_r < 67 && c >= 3 && c < 67)
                acg[gr*IMG + gc] = ac;
            if (k + 1 < cnt) s += H1[(la_r+8)*H1S + c] - H1[la_r*H1S + c];
        }
    }
    __syncthreads();

    // H2[r][c2] = sum_{d} AC[r][c2+d]^2, r in [0,71), c2 in [0,64)
    for (int idx = tid; idx < AR*4; idx += 256) {
        int r = idx >> 2, q = idx & 3;
        int c0 = q * 16;
        const float* ar = AC + r*ACS + c0;
        float w[23];
        #pragma unroll
        for (int d = 0; d < 23; d++) { float v = ar[d]; w[d] = v*v; }
        float s = 0.f;
        #pragma unroll
        for (int d = 0; d < 8; d++) s += w[d];
        float* hr = H2 + r*H2S + c0;
        hr[0] = s;
        #pragma unroll
        for (int k = 1; k < 16; k++) { s += w[k+7] - w[k-1]; hr[k] = s; }
    }
    __syncthreads();

    // V2: sii = max(vert-sum, EPS), coalesced store
    {
        int c = tid % 64, g = tid / 64;
        float ps[24];
        ps[0] = 0.f;
        #pragma unroll
        for (int k = 0; k < 23; k++) ps[k+1] = ps[k] + H2[(g*16+k)*H2S + c];
        #pragma unroll
        for (int k = 0; k < 16; k++) {
            float v = fmaxf(ps[k+8] - ps[k], EPS);
            sg[(ty0 + g*16 + k)*IMG + tx0 + c] = v;
        }
    }
}

// =========================================================================
// pair: per (b,o) tile, loop labels, cc = box(ac*bc)/(sqrt(sii*sjj)+EPS),
//       running max, X = 1 - min(1, max), fixed-slot partial sums.
// grid: (8, 8, 24)  z = b*6 + o
// =========================================================================
__global__ __launch_bounds__(256)
void pair_kernel() {
    extern __shared__ float sm[];
    float* AC  = sm;                 // AR*ACS
    float* BC  = AC + AR*ACS;        // AR*ACS
    float* Hs  = BC + AR*ACS;        // AR*HSS
    float* red = Hs + AR*HSS;        // 256

    int tx0 = blockIdx.x * TILE, ty0 = blockIdx.y * TILE;
    int z = blockIdx.z;
    int b = z / NO;
    const float* acg  = d_ac  + (size_t)z*NPIX;
    const float* siig = d_sii + (size_t)z*NPIX;
    int tid = threadIdx.x;

    for (int idx = tid; idx < AR*AR; idx += 256) {
        int r = idx / AR, c = idx % AR;
        int gr = ty0 + r - 3, gc = tx0 + c - 3;
        float v = 0.f;
        if ((unsigned)gr < (unsigned)IMG && (unsigned)gc < (unsigned)IMG) v = acg[gr*IMG + gc];
        AC[r*ACS + c] = v;
    }

    int cl = tid % 64, g = tid / 64;
    float siiR[16], maxcc[16];
    #pragma unroll
    for (int k = 0; k < 16; k++) {
        siiR[k] = siig[(ty0 + g*16 + k)*IMG + tx0 + cl];
        maxcc[k] = -1.0f;
    }

    for (int l = 0; l < NL; l++) {
        const float* bcg  = d_bc  + (size_t)(b*NL + l)*NPIX;
        const float* sjjg = d_sjj + (size_t)(b*NL + l)*NPIX;
        __syncthreads();   // protect BC/Hs reuse (also covers AC on first iter)
        for (int idx = tid; idx < AR*AR; idx += 256) {
            int r = idx / AR, c = idx % AR;
            int gr = ty0 + r - 3, gc = tx0 + c - 3;
            float v = 0.f;
            if ((unsigned)gr < (unsigned)IMG && (unsigned)gc < (unsigned)IMG) v = bcg[gr*IMG + gc];
            BC[r*ACS + c] = v;
        }
        __syncthreads();

        // Hs[r][c2] = sum_{d} AC[r][c2+d]*BC[r][c2+d]
        for (int idx = tid; idx < AR*4; idx += 256) {
            int r = idx >> 2, q = idx & 3;
            int c0 = q * 16;
            const float* ar = AC + r*ACS + c0;
            const float* br = BC + r*ACS + c0;
            float w[23];
            #pragma unroll
            for (int d = 0; d < 23; d++) w[d] = ar[d] * br[d];
            float s = 0.f;
            #pragma unroll
            for (int d = 0; d < 8; d++) s += w[d];
            float* hr = Hs + r*HSS + c0;
            hr[0] = s;
            #pragma unroll
            for (int k = 1; k < 16; k++) { s += w[k+7] - w[k-1]; hr[k] = s; }
        }
        __syncthreads();

        // vertical sums + cc + running max
        float sjjR[16];
        #pragma unroll
        for (int k = 0; k < 16; k++)
            sjjR[k] = sjjg[(ty0 + g*16 + k)*IMG + tx0 + cl];
        float ps[24];
        ps[0] = 0.f;
        #pragma unroll
        for (int k = 0; k < 23; k++) ps[k+1] = ps[k] + Hs[(g*16+k)*HSS + cl];
        #pragma unroll
        for (int k = 0; k < 16; k++) {
            float sij = ps[k+8] - ps[k];
            float cc  = sij / (sqrtf(siiR[k] * sjjR[k]) + EPS);
            maxcc[k]  = fmaxf(maxcc[k], cc);
        }
    }

    float local = 0.f;
    #pragma unroll
    for (int k = 0; k < 16; k++) local += 1.0f - fminf(1.0f, maxcc[k]);

    red[tid] = local;
    __syncthreads();
    #pragma unroll
    for (int s = 128; s > 0; s >>= 1) {
        if (tid < s) red[tid] += red[tid + s];
        __syncthreads();
    }
    if (tid == 0) d_partial[z*64 + blockIdx.y*8 + blockIdx.x] = red[0];
}

// =========================================================================
// finalize: deterministic fixed-order sums -> out[0]=mean, out[1..24]=per(b,o)
// =========================================================================
__global__ void finalize_kernel(float* __restrict__ out, int out_size) {
    __shared__ float vals[NB*NO];
    int t = threadIdx.x;
    if (t < NB*NO) {
        float s = 0.f;
        for (int i = 0; i < 64; i++) s += d_partial[t*64 + i];
        float m = s * (1.0f / (float)NPIX);
        vals[t] = m;
        if (1 + t < out_size) out[1 + t] = m;
    }
    __syncthreads();
    if (t == 0) {
        float s = 0.f;
        for (int i = 0; i < NB*NO; i++) s += vals[i];
        if (out_size > 0) out[0] = s / (float)(NB*NO);
    }
}

extern "C" void kernel_launch(void* const* d_in, const int* in_sizes, int n_in,
                              void* d_out, int out_size) {
    const float* outs = (const float*)d_in[0];
    const float* labs = (const float*)d_in[1];
    if (n_in >= 2 && in_sizes[0] < in_sizes[1]) {  // defensive: outputs is the larger tensor
        const float* tmp = outs; outs = labs; labs = tmp;
    }

    const int PREP_SMEM = (XR*XS + XR*H1S + AR*ACS + AR*H2S) * (int)sizeof(float);   // ~86 KB
    const int PAIR_SMEM = (AR*ACS*2 + AR*HSS + 256) * (int)sizeof(float);            // ~60 KB

    cudaFuncSetAttribute(prep_kernel, cudaFuncAttributeMaxDynamicSharedMemorySize, PREP_SMEM);
    cudaFuncSetAttribute(pair_kernel, cudaFuncAttributeMaxDynamicSharedMemorySize, PAIR_SMEM);

    prep_kernel<<<dim3(8, 8, NB*NO + NB*NL), 256, PREP_SMEM>>>(outs, labs);
    pair_kernel<<<dim3(8, 8, NB*NO), 256, PAIR_SMEM>>>();
    finalize_kernel<<<1, 32>>>((float*)d_out, out_size);
}

// round 2
// speedup vs baseline: 1.2621x; 1.2621x over previous
#include <cuda_runtime.h>
#include <math.h>

#define IMG   512
#define NPIX  (IMG*IMG)
#define NB    4
#define NO    6
#define NL    4
#define TILE  64
#define TS    71      // tile+7 (ac/bc extent and stride, odd -> conflict-free)
#define XR    78      // tile+14 (raw tile with double halo)
#define XS2   79      // raw tile stride (odd)
#define EPS   1e-20f

// sizes in floats
#define SZ_BC   (TS*TS)        // 5041
#define SZ_SJJ  (TILE*TILE)    // 4096
#define SZ_X    (XR*XS2)       // 6162
#define SZ_H    (XR*TS)        // 5538
#define SMEM_FLOATS (NL*SZ_BC + NL*SZ_SJJ + SZ_BC + SZ_X + SZ_H)   // 53289

__device__ float d_partial[NB*NO*64];

// ---- load raw 78x78 tile (zero outside image) ----
__device__ __forceinline__ void load_tile(const float* __restrict__ src, float* X,
                                          int tx0, int ty0, int tid) {
    for (int idx = tid; idx < XR*XR; idx += 256) {
        int r = idx / XR, c = idx % XR;
        int gr = ty0 + r - 6, gc = tx0 + c - 6;
        float v = 0.f;
        if ((unsigned)gr < (unsigned)IMG && (unsigned)gc < (unsigned)IMG)
            v = __ldg(src + gr*IMG + gc);
        X[r*XS2 + c] = v;
    }
}

// ---- H[r][c] = sum_{d=0..7} X[r][c+d], r<78, c<71 ----
__device__ __forceinline__ void hmean(const float* X, float* H, int tid) {
    for (int idx = tid; idx < XR*4; idx += 256) {
        int r = idx % XR, q = idx / XR;
        int c0 = q * 18, cnt = min(18, TS - c0);
        const float* xr = X + r*XS2 + c0;
        float s = xr[0]+xr[1]+xr[2]+xr[3]+xr[4]+xr[5]+xr[6]+xr[7];
        float* hr = H + r*TS + c0;
        hr[0] = s;
        for (int k = 1; k < cnt; k++) { s += xr[k+7] - xr[k-1]; hr[k] = s; }
    }
}

// ---- OUT[r][c] = inside ? X[r+3][c+3] - mean : 0,  r,c < 71 ----
__device__ __forceinline__ void centered(const float* X, const float* H, float* OUT,
                                         int tx0, int ty0, int tid) {
    for (int idx = tid; idx < TS*4; idx += 256) {
        int c = idx % TS, q = idx / TS;
        int r0 = q * 18, cnt = min(18, TS - r0);
        float s = 0.f;
        #pragma unroll
        for (int d = 0; d < 8; d++) s += H[(r0+d)*TS + c];
        for (int k = 0; k < cnt; k++) {
            int r = r0 + k;
            int gr = ty0 + r - 3, gc = tx0 + c - 3;
            float v = 0.f;
            if ((unsigned)gr < (unsigned)IMG && (unsigned)gc < (unsigned)IMG)
                v = X[(r+3)*XS2 + (c+3)] - s * (1.f/64.f);
            OUT[r*TS + c] = v;
            if (k + 1 < cnt) s += H[(r+8)*TS + c] - H[r*TS + c];
        }
    }
}

// ---- H[r][c2] = sum_{d=0..7} A[r][c2+d]*B[r][c2+d], r<71, c2<64 ----
__device__ __forceinline__ void hprod(const float* A, const float* B, float* H, int tid) {
    for (int idx = tid; idx < TS*4; idx += 256) {
        int r = idx % TS, q = idx / TS;
        int c0 = q * 16;
        const float* ar = A + r*TS + c0;
        const float* br = B + r*TS + c0;
        float w[23];
        #pragma unroll
        for (int d = 0; d < 23; d++) w[d] = ar[d] * br[d];
        float s = w[0]+w[1]+w[2]+w[3]+w[4]+w[5]+w[6]+w[7];
        float* hr = H + r*TS + c0;
        hr[0] = s;
        #pragma unroll
        for (int k = 1; k < 16; k++) { s += w[k+7] - w[k-1]; hr[k] = s; }
    }
}

// ---- 16 vertical window sums of H at column cl, row group g ----
__device__ __forceinline__ void vsum16(const float* H, int g, int cl, float* out) {
    float ps[24];
    ps[0] = 0.f;
    #pragma unroll
    for (int k = 0; k < 23; k++) ps[k+1] = ps[k] + H[(g*16 + k)*TS + cl];
    #pragma unroll
    for (int k = 0; k < 16; k++) out[k] = ps[k+8] - ps[k];
}

// =========================================================================
// fused: one CTA per (batch, 64x64 tile). Caches bc/sjj for all 4 labels in
// smem, then streams the 6 outputs; inner sij loop touches smem only.
// =========================================================================
__global__ void __launch_bounds__(256, 1)
fused_kernel(const float* __restrict__ outs, const float* __restrict__ labs) {
    extern __shared__ float sm[];
    float* BC  = sm;                         // NL * 5041
    float* SJJ = BC  + NL*SZ_BC;             // NL * 4096
    float* AC  = SJJ + NL*SZ_SJJ;            // 5041
    float* X   = AC  + SZ_BC;                // 6162  (also reduction scratch)
    float* H   = X   + SZ_X;                 // 5538  (hosts H1 / H^2 / Hs)

    int tx0 = blockIdx.x * TILE, ty0 = blockIdx.y * TILE;
    int b = blockIdx.z;
    int tid = threadIdx.x;
    int cl = tid & 63, g = tid >> 6;
    int lane = tid & 31, wid = tid >> 5;

    // ---- phase 1: labels -> BC[l], SJJ[l] ----
    for (int l = 0; l < NL; l++) {
        load_tile(labs + (size_t)(b*NL + l)*NPIX, X, tx0, ty0, tid);
        __syncthreads();
        hmean(X, H, tid);
        __syncthreads();
        centered(X, H, BC + l*SZ_BC, tx0, ty0, tid);
        __syncthreads();
        hprod(BC + l*SZ_BC, BC + l*SZ_BC, H, tid);
        __syncthreads();
        {
            float v16[16];
            vsum16(H, g, cl, v16);
            #pragma unroll
            for (int k = 0; k < 16; k++)
                SJJ[l*SZ_SJJ + (g*16 + k)*TILE + cl] = fmaxf(v16[k], EPS);
        }
        __syncthreads();   // H reused next iteration
    }

    // ---- phase 2: outputs ----
    for (int o = 0; o < NO; o++) {
        load_tile(outs + (size_t)(b*NO + o)*NPIX, X, tx0, ty0, tid);
        __syncthreads();
        hmean(X, H, tid);
        __syncthreads();
        centered(X, H, AC, tx0, ty0, tid);
        __syncthreads();
        hprod(AC, AC, H, tid);
        __syncthreads();

        float siiR[16];
        vsum16(H, g, cl, siiR);
        #pragma unroll
        for (int k = 0; k < 16; k++) siiR[k] = fmaxf(siiR[k], EPS);

        float maxcc[16];
        #pragma unroll
        for (int k = 0; k < 16; k++) maxcc[k] = -1.0f;

        for (int l = 0; l < NL; l++) {
            __syncthreads();               // protect H (prev vsum read it)
            hprod(AC, BC + l*SZ_BC, H, tid);
            __syncthreads();
            float sij16[16];
            vsum16(H, g, cl, sij16);
            #pragma unroll
            for (int k = 0; k < 16; k++) {
                float sjj = SJJ[l*SZ_SJJ + (g*16 + k)*TILE + cl];
                float cc  = sij16[k] / (sqrtf(siiR[k] * sjj) + EPS);
                maxcc[k]  = fmaxf(maxcc[k], cc);
            }
        }

        // per-(b,o) tile sum of X = 1 - min(1, maxcc)
        float local = 0.f;
        #pragma unroll
        for (int k = 0; k < 16; k++) local += 1.0f - fminf(1.0f, maxcc[k]);

        #pragma unroll
        for (int off = 16; off > 0; off >>= 1)
            local += __shfl_down_sync(0xFFFFFFFFu, local, off);
        __syncthreads();                   // X dead; reuse as reduction scratch
        if (lane == 0) X[wid] = local;
        __syncthreads();
        if (tid == 0) {
            float s = 0.f;
            #pragma unroll
            for (int w = 0; w < 8; w++) s += X[w];
            d_partial[(b*NO + o)*64 + blockIdx.y*8 + blockIdx.x] = s;
        }
        __syncthreads();                   // before X is reloaded next o
    }
}

// =========================================================================
// finalize: deterministic fixed-order sums -> out[0]=mean, out[1..24]=per(b,o)
// =========================================================================
__global__ void finalize_kernel(float* __restrict__ out, int out_size) {
    __shared__ float vals[NB*NO];
    int t = threadIdx.x;
    if (t < NB*NO) {
        float s = 0.f;
        for (int i = 0; i < 64; i++) s += d_partial[t*64 + i];
        float m = s * (1.0f / (float)NPIX);
        vals[t] = m;
        if (1 + t < out_size) out[1 + t] = m;
    }
    __syncthreads();
    if (t == 0) {
        float s = 0.f;
        for (int i = 0; i < NB*NO; i++) s += vals[i];
        if (out_size > 0) out[0] = s / (float)(NB*NO);
    }
}

extern "C" void kernel_launch(void* const* d_in, const int* in_sizes, int n_in,
                              void* d_out, int out_size) {
    const float* outs = (const float*)d_in[0];
    const float* labs = (const float*)d_in[1];
    if (n_in >= 2 && in_sizes[0] < in_sizes[1]) {  // defensive: outputs is the larger tensor
        const float* tmp = outs; outs = labs; labs = tmp;
    }

    const int SMEM = SMEM_FLOATS * (int)sizeof(float);   // 213,156 B
    cudaFuncSetAttribute(fused_kernel, cudaFuncAttributeMaxDynamicSharedMemorySize, SMEM);

    fused_kernel<<<dim3(8, 8, NB), 256, SMEM>>>(outs, labs);
    finalize_kernel<<<1, 32>>>((float*)d_out, out_size);
}

// round 3
// speedup vs baseline: 1.7872x; 1.4160x over previous
#include <cuda_runtime.h>
#include <math.h>

#define IMG   512
#define NPIX  (IMG*IMG)
#define NB    4
#define NO    6
#define NL    4
#define TILE  64
#define TS    71      // tile+7 (ac/bc extent and stride; 71 mod 32 = 7, conflict-free)
#define XR    78      // tile+14 (raw tile with double halo)
#define XS2   79      // raw tile stride (79 mod 32 = 15, conflict-free)
#define EPS   1e-20f
#define NT    512

// sizes in floats
#define SZ_BC   (TS*TS)        // 5041
#define SZ_SJJ  (TILE*TILE)    // 4096
#define SZ_X    (XR*XS2)       // 6162  (>= SZ_H so it can host the 2nd H buffer)
#define SZ_H    (XR*TS)        // 5538
#define SMEM_FLOATS (NL*SZ_BC + NL*SZ_SJJ + SZ_BC + SZ_X + SZ_H)   // 53289

__device__ float d_partial[NB*NO*64];

// ---- load raw 78x78 tile (zero outside image) ----
__device__ __forceinline__ void load_tile(const float* __restrict__ src, float* __restrict__ X,
                                          int tx0, int ty0, int tid) {
    for (int idx = tid; idx < XR*XR; idx += NT) {
        int r = idx / XR, c = idx % XR;
        int gr = ty0 + r - 6, gc = tx0 + c - 6;
        float v = 0.f;
        if ((unsigned)gr < (unsigned)IMG && (unsigned)gc < (unsigned)IMG)
            v = __ldg(src + gr*IMG + gc);
        X[r*XS2 + c] = v;
    }
}

// ---- H[r][c] = sum_{d=0..7} X[r][c+d], r<78, c<71.  624 items, reg-staged ----
__device__ __forceinline__ void hmean(const float* __restrict__ X, float* __restrict__ H, int tid) {
    for (int idx = tid; idx < XR*8; idx += NT) {
        int r = idx % XR, q = idx / XR;
        int c0 = q * 9;
        int cnt = (q == 7) ? 8 : 9;
        const float* xr = X + r*XS2 + c0;
        float w[16];
        #pragma unroll
        for (int d = 0; d < 16; d++) w[d] = xr[d];       // col<=78 < stride 79: safe
        float s = w[0]+w[1]+w[2]+w[3]+w[4]+w[5]+w[6]+w[7];
        float* hr = H + r*TS + c0;
        hr[0] = s;
        #pragma unroll
        for (int k = 1; k < 9; k++) {
            if (k < cnt) { s += w[k+7] - w[k-1]; hr[k] = s; }
        }
    }
}

// ---- OUT[r][c] = inside ? X[r+3][c+3] - boxmean : 0,  r,c<71.  568 items ----
__device__ __forceinline__ void centered(const float* __restrict__ X, const float* __restrict__ H,
                                         float* __restrict__ OUT, int tx0, int ty0, int tid) {
    for (int idx = tid; idx < TS*8; idx += NT) {
        int c = idx % TS, q = idx / TS;
        int r0 = q * 9;
        int cnt = (q == 7) ? 8 : 9;
        float h[16];
        #pragma unroll
        for (int d = 0; d < 16; d++) h[d] = H[min(r0 + d, 77)*TS + c];   // clamp keeps in-bounds
        float xv[9];
        #pragma unroll
        for (int k = 0; k < 9; k++) xv[k] = X[(r0 + k + 3)*XS2 + (c + 3)];  // max row 74 < 78
        float s = h[0]+h[1]+h[2]+h[3]+h[4]+h[5]+h[6]+h[7];
        int gc = tx0 + c - 3;
        bool cin = (unsigned)gc < (unsigned)IMG;
        #pragma unroll
        for (int k = 0; k < 9; k++) {
            if (k < cnt) {
                int r = r0 + k;
                int gr = ty0 + r - 3;
                float v = 0.f;
                if (cin && (unsigned)gr < (unsigned)IMG) v = xv[k] - s * (1.f/64.f);
                OUT[r*TS + c] = v;
                if (k + 1 < cnt) s += h[k+8] - h[k];
            }
        }
    }
}

// ---- H[r][c2] = sum_{d=0..7} A[r][c2+d]*B[r][c2+d], r<71, c2<64.  568 items ----
__device__ __forceinline__ void hprod(const float* __restrict__ A, const float* __restrict__ B,
                                      float* __restrict__ H, int tid) {
    for (int idx = tid; idx < TS*8; idx += NT) {
        int r = idx % TS, q = idx / TS;
        int c0 = q * 8;                          // max 56, window to col 70
        const float* ar = A + r*TS + c0;
        const float* br = B + r*TS + c0;
        float w[15];
        #pragma unroll
        for (int d = 0; d < 15; d++) w[d] = ar[d] * br[d];
        float s = w[0]+w[1]+w[2]+w[3]+w[4]+w[5]+w[6]+w[7];
        float* hr = H + r*TS + c0;
        hr[0] = s;
        #pragma unroll
        for (int k = 1; k < 8; k++) { s += w[k+7] - w[k-1]; hr[k] = s; }
    }
}

// ---- 8 vertical window sums of H at column cl, row group g (rows g*8..g*8+7) ----
__device__ __forceinline__ void vsum8(const float* __restrict__ H, int g, int cl, float* out) {
    float ps[16];
    ps[0] = 0.f;
    #pragma unroll
    for (int k = 0; k < 15; k++) ps[k+1] = ps[k] + H[(g*8 + k)*TS + cl];
    #pragma unroll
    for (int k = 0; k < 8; k++) out[k] = ps[k+8] - ps[k];
}

// =========================================================================
// fused: one CTA per (batch, 64x64 tile), 512 threads.
// =========================================================================
__global__ void __launch_bounds__(NT, 1)
fused_kernel(const float* __restrict__ outs, const float* __restrict__ labs) {
    extern __shared__ float sm[];
    float* BC  = sm;                         // NL * 5041
    float* SJJ = BC  + NL*SZ_BC;             // NL * 4096
    float* AC  = SJJ + NL*SZ_SJJ;            // 5041 (also 16-float reduction scratch)
    float* X   = AC  + SZ_BC;                // 6162 (raw tile; also 2nd H buffer in sij loop)
    float* H   = X   + SZ_X;                 // 5538

    int tx0 = blockIdx.x * TILE, ty0 = blockIdx.y * TILE;
    int b = blockIdx.z;
    int tid = threadIdx.x;
    int cl = tid & 63, g = tid >> 6;         // g in 0..7
    int lane = tid & 31, wid = tid >> 5;

    // ---- phase 1: labels -> BC[l], SJJ[l] ----
    for (int l = 0; l < NL; l++) {
        load_tile(labs + (size_t)(b*NL + l)*NPIX, X, tx0, ty0, tid);
        __syncthreads();
        hmean(X, H, tid);
        __syncthreads();
        centered(X, H, BC + l*SZ_BC, tx0, ty0, tid);
        __syncthreads();
        hprod(BC + l*SZ_BC, BC + l*SZ_BC, H, tid);
        __syncthreads();
        float v8[8];
        vsum8(H, g, cl, v8);
        #pragma unroll
        for (int k = 0; k < 8; k++)
            SJJ[l*SZ_SJJ + (g*8 + k)*TILE + cl] = fmaxf(v8[k], EPS);
        // no trailing sync needed: next load_tile writes X (not read by vsum);
        // H is rewritten by hmean only after two barriers.
    }

    // ---- phase 2: outputs ----
    for (int o = 0; o < NO; o++) {
        load_tile(outs + (size_t)(b*NO + o)*NPIX, X, tx0, ty0, tid);
        __syncthreads();
        hmean(X, H, tid);
        __syncthreads();
        centered(X, H, AC, tx0, ty0, tid);
        __syncthreads();
        hprod(AC, AC, H, tid);
        __syncthreads();

        float siiR[8];
        vsum8(H, g, cl, siiR);
        #pragma unroll
        for (int k = 0; k < 8; k++) siiR[k] = fmaxf(siiR[k], EPS);

        float maxcc[8];
        #pragma unroll
        for (int k = 0; k < 8; k++) maxcc[k] = -1.0f;

        // sij loop: ping-pong H between X-region (even l) and H (odd l).
        // One barrier per label; the barrier at label l also retires the
        // buffer readers from label l-1 before label l+1 overwrites it.
        for (int l = 0; l < NL; l++) {
            float* Hb = (l & 1) ? H : X;
            hprod(AC, BC + l*SZ_BC, Hb, tid);
            __syncthreads();
            float sij8[8];
            vsum8(Hb, g, cl, sij8);
            #pragma unroll
            for (int k = 0; k < 8; k++) {
                float sjj = SJJ[l*SZ_SJJ + (g*8 + k)*TILE + cl];
                float cc  = sij8[k] / (sqrtf(siiR[k] * sjj) + EPS);
                maxcc[k]  = fmaxf(maxcc[k], cc);
            }
        }

        // per-(b,o) tile sum of Xv = 1 - min(1, maxcc)
        float local = 0.f;
        #pragma unroll
        for (int k = 0; k < 8; k++) local += 1.0f - fminf(1.0f, maxcc[k]);
        #pragma unroll
        for (int off = 16; off > 0; off >>= 1)
            local += __shfl_down_sync(0xFFFFFFFFu, local, off);
        if (lane == 0) AC[wid] = local;      // AC's hprod readers retired at l=3 barrier
        __syncthreads();
        if (tid == 0) {
            float s = 0.f;
            #pragma unroll
            for (int w2 = 0; w2 < 16; w2++) s += AC[w2];
            d_partial[(b*NO + o)*64 + blockIdx.y*8 + blockIdx.x] = s;
        }
        // no trailing sync: next load_tile writes X, whose readers (vsum l=2)
        // retired at the l=3 barrier; AC scratch reads complete before tid 0
        // can pass the next load barrier.
    }
}

// =========================================================================
// finalize: deterministic fixed-order sums -> out[0]=mean, out[1..24]=per(b,o)
// =========================================================================
__global__ void finalize_kernel(float* __restrict__ out, int out_size) {
    __shared__ float vals[NB*NO];
    int t = threadIdx.x;
    if (t < NB*NO) {
        float s = 0.f;
        for (int i = 0; i < 64; i++) s += d_partial[t*64 + i];
        float m = s * (1.0f / (float)NPIX);
        vals[t] = m;
        if (1 + t < out_size) out[1 + t] = m;
    }
    __syncthreads();
    if (t == 0) {
        float s = 0.f;
        for (int i = 0; i < NB*NO; i++) s += vals[i];
        if (out_size > 0) out[0] = s / (float)(NB*NO);
    }
}

extern "C" void kernel_launch(void* const* d_in, const int* in_sizes, int n_in,
                              void* d_out, int out_size) {
    const float* outs = (const float*)d_in[0];
    const float* labs = (const float*)d_in[1];
    if (n_in >= 2 && in_sizes[0] < in_sizes[1]) {  // defensive: outputs is the larger tensor
        const float* tmp = outs; outs = labs; labs = tmp;
    }

    const int SMEM = SMEM_FLOATS * (int)sizeof(float);   // 213,156 B
    cudaFuncSetAttribute(fused_kernel, cudaFuncAttributeMaxDynamicSharedMemorySize, SMEM);

    fused_kernel<<<dim3(8, 8, NB), NT, SMEM>>>(outs, labs);
    finalize_kernel<<<1, 32>>>((float*)d_out, out_size);
}

// round 4
// speedup vs baseline: 1.9295x; 1.0796x over previous
#include <cuda_runtime.h>
#include <math.h>

#define IMG   512
#define NPIX  (IMG*IMG)
#define NB    4
#define NO    6
#define NL    4
#define TILE  64
#define TS    71      // bc/ac extent+stride (71 mod 32 = 7 -> conflict-free)
#define XR    78      // raw tile rows/cols (double halo)
#define XS2   79      // raw tile stride (odd)
#define HS    65      // H box-buffer stride (odd), 71 rows x 64 cols used
#define EPS   1e-20f
#define NT    512
#define NCTA  (8*8*NB)   // 256

// sizes in floats
#define SZ_BC   (TS*TS)        // 5041
#define SZ_X    (XR*XS2)       // 6162
#define SZ_HM   (XR*TS)        // 5538 (hmean out: 78 rows x 71 cols)
#define SZ_HB   (TS*HS)        // 4615 (one box buffer)
#define R_FLOATS (5*SZ_HB)     // 23075 >= SZ_X+SZ_HM (11700)
#define SMEM_FLOATS (NL*SZ_BC + SZ_BC + R_FLOATS)   // 48280 -> 193,120 B

__device__ float d_partial[NB*NO*64];
__device__ unsigned int d_count = 0;

// ---- load raw 78x78 tile (zero outside image) ----
__device__ __forceinline__ void load_tile(const float* __restrict__ src, float* __restrict__ X,
                                          int tx0, int ty0, int tid) {
    for (int idx = tid; idx < XR*XR; idx += NT) {
        int r = idx / XR, c = idx % XR;
        int gr = ty0 + r - 6, gc = tx0 + c - 6;
        float v = 0.f;
        if ((unsigned)gr < (unsigned)IMG && (unsigned)gc < (unsigned)IMG)
            v = __ldg(src + gr*IMG + gc);
        X[r*XS2 + c] = v;
    }
}

// ---- Hm[r][c] = sum_{d=0..7} X[r][c+d], r<78, c<71 (reg-staged) ----
__device__ __forceinline__ void hmean(const float* __restrict__ X, float* __restrict__ Hm, int tid) {
    for (int idx = tid; idx < XR*8; idx += NT) {
        int r = idx % XR, q = idx / XR;
        int c0 = q * 9;
        int cnt = (q == 7) ? 8 : 9;
        const float* xr = X + r*XS2 + c0;
        float w[16];
        #pragma unroll
        for (int d = 0; d < 16; d++) w[d] = xr[d];         // col <= 78 < stride 79
        float s = w[0]+w[1]+w[2]+w[3]+w[4]+w[5]+w[6]+w[7];
        float* hr = Hm + r*TS + c0;
        hr[0] = s;
        #pragma unroll
        for (int k = 1; k < 9; k++)
            if (k < cnt) { s += w[k+7] - w[k-1]; hr[k] = s; }
    }
}

// ---- OUT[r][c] = inside ? X[r+3][c+3] - boxmean : 0, r,c<71 ----
__device__ __forceinline__ void centered(const float* __restrict__ X, const float* __restrict__ Hm,
                                         float* __restrict__ OUT, int tx0, int ty0, int tid) {
    for (int idx = tid; idx < TS*8; idx += NT) {
        int c = idx % TS, q = idx / TS;
        int r0 = q * 9;
        int cnt = (q == 7) ? 8 : 9;
        float h[16];
        #pragma unroll
        for (int d = 0; d < 16; d++) h[d] = Hm[min(r0 + d, 77)*TS + c];
        float xv[9];
        #pragma unroll
        for (int k = 0; k < 9; k++) xv[k] = X[(r0 + k + 3)*XS2 + (c + 3)];
        float s = h[0]+h[1]+h[2]+h[3]+h[4]+h[5]+h[6]+h[7];
        int gc = tx0 + c - 3;
        bool cin = (unsigned)gc < (unsigned)IMG;
        #pragma unroll
        for (int k = 0; k < 9; k++) {
            if (k < cnt) {
                int r = r0 + k;
                int gr = ty0 + r - 3;
                float v = 0.f;
                if (cin && (unsigned)gr < (unsigned)IMG) v = xv[k] - s * (1.f/64.f);
                OUT[r*TS + c] = v;
                if (k + 1 < cnt) s += h[k+8] - h[k];
            }
        }
    }
}

// ---- 8 vertical window sums of Hb at column cl, row group g ----
__device__ __forceinline__ void vsum8(const float* __restrict__ Hb, int g, int cl, float* out) {
    float ps[16];
    ps[0] = 0.f;
    #pragma unroll
    for (int k = 0; k < 15; k++) ps[k+1] = ps[k] + Hb[(g*8 + k)*HS + cl];
    #pragma unroll
    for (int k = 0; k < 8; k++) out[k] = ps[k+8] - ps[k];
}

// =========================================================================
// fused: one CTA per (batch, 64x64 tile), 512 threads, finalize in-kernel.
// =========================================================================
__global__ void __launch_bounds__(NT, 1)
fused_kernel(const float* __restrict__ outs, const float* __restrict__ labs,
             float* __restrict__ out, int out_size) {
    extern __shared__ float sm[];
    float* BC = sm;                  // NL * 5041
    float* AC = BC + NL*SZ_BC;       // 5041 (tail doubles as reduction scratch)
    float* R  = AC + SZ_BC;          // 23075: prep {X, Hm} / corr {H0..H4}
    float* X  = R;                   // 6162, stride 79
    float* Hm = R + SZ_X;            // 5538, stride 71
    __shared__ unsigned int s_flag;
    __shared__ float s_vals[NB*NO];

    int tx0 = blockIdx.x * TILE, ty0 = blockIdx.y * TILE;
    int b = blockIdx.z;
    int tid = threadIdx.x;
    int cl = tid & 63, g = tid >> 6;      // pixel column / row-group
    int lane = tid & 31, wid = tid >> 5;

    // ---------------- phase 1: labels -> BC[l] and sjj regs ----------------
    for (int l = 0; l < NL; l++) {
        load_tile(labs + (size_t)(b*NL + l)*NPIX, X, tx0, ty0, tid);
        __syncthreads();
        hmean(X, Hm, tid);
        __syncthreads();
        centered(X, Hm, BC + l*SZ_BC, tx0, ty0, tid);
        __syncthreads();   // BC[l] ready; also retires X/Hm before next load
    }

    // one wide hprod phase: box-row sums of bc_l^2 for all 4 labels
    for (int idx = tid; idx < NL*TS*8; idx += NT) {
        int l = idx / (TS*8), rem = idx % (TS*8);
        int r = rem % TS, q = rem / TS;
        int c0 = q * 8;
        const float* ar = BC + l*SZ_BC + r*TS + c0;
        float w[15];
        #pragma unroll
        for (int d = 0; d < 15; d++) { float v = ar[d]; w[d] = v*v; }
        float s = w[0]+w[1]+w[2]+w[3]+w[4]+w[5]+w[6]+w[7];
        float* hr = R + l*SZ_HB + r*HS + c0;
        hr[0] = s;
        #pragma unroll
        for (int k = 1; k < 8; k++) { s += w[k+7] - w[k-1]; hr[k] = s; }
    }
    __syncthreads();

    float sjjR[NL][8];
    #pragma unroll
    for (int l = 0; l < NL; l++) {
        float v8[8];
        vsum8(R + l*SZ_HB, g, cl, v8);
        #pragma unroll
        for (int k = 0; k < 8; k++) sjjR[l][k] = fmaxf(v8[k], EPS);
    }
    __syncthreads();   // sjj in regs; R region free for phase 2

    // ---------------- phase 2: outputs ----------------
    for (int o = 0; o < NO; o++) {
        load_tile(outs + (size_t)(b*NO + o)*NPIX, X, tx0, ty0, tid);
        __syncthreads();
        hmean(X, Hm, tid);
        __syncthreads();
        centered(X, Hm, AC, tx0, ty0, tid);
        __syncthreads();   // AC ready; X/Hm dead -> R hosts H0..H4

        // one wide phase: j=0 -> ac*ac, j=1..4 -> ac*bc_{j-1}
        for (int idx = tid; idx < 5*TS*8; idx += NT) {
            int j = idx / (TS*8), rem = idx % (TS*8);
            int r = rem % TS, q = rem / TS;
            int c0 = q * 8;
            const float* ar = AC + r*TS + c0;
            const float* br = (j == 0) ? ar : (BC + (j-1)*SZ_BC + r*TS + c0);
            float w[15];
            #pragma unroll
            for (int d = 0; d < 15; d++) w[d] = ar[d] * br[d];
            float s = w[0]+w[1]+w[2]+w[3]+w[4]+w[5]+w[6]+w[7];
            float* hr = R + j*SZ_HB + r*HS + c0;
            hr[0] = s;
            #pragma unroll
            for (int k = 1; k < 8; k++) { s += w[k+7] - w[k-1]; hr[k] = s; }
        }
        __syncthreads();

        float siiR[8];
        vsum8(R, g, cl, siiR);
        #pragma unroll
        for (int k = 0; k < 8; k++) siiR[k] = fmaxf(siiR[k], EPS);

        float maxcc[8];
        #pragma unroll
        for (int k = 0; k < 8; k++) maxcc[k] = -1.0f;

        #pragma unroll
        for (int l = 0; l < NL; l++) {
            float sij8[8];
            vsum8(R + (l+1)*SZ_HB, g, cl, sij8);
            #pragma unroll
            for (int k = 0; k < 8; k++) {
                float cc = sij8[k] / (sqrtf(siiR[k] * sjjR[l][k]) + EPS);
                maxcc[k] = fmaxf(maxcc[k], cc);
            }
        }

        float local = 0.f;
        #pragma unroll
        for (int k = 0; k < 8; k++) local += 1.0f - fminf(1.0f, maxcc[k]);
        #pragma unroll
        for (int off = 16; off > 0; off >>= 1)
            local += __shfl_down_sync(0xFFFFFFFFu, local, off);
        if (lane == 0) AC[wid] = local;   // AC readers (hprod) retired above
        __syncthreads();                  // also retires H reads before next load
        if (tid == 0) {
            float s = 0.f;
            #pragma unroll
            for (int w2 = 0; w2 < 16; w2++) s += AC[w2];
            d_partial[(b*NO + o)*64 + blockIdx.y*8 + blockIdx.x] = s;
        }
        // next load_tile writes R (disjoint from AC scratch); tid0 rejoins at
        // the post-load barrier, so its AC reads precede the next centered.
    }

    // ---------------- in-kernel finalize (last CTA, fixed-order sums) ------
    if (tid == 0) {
        __threadfence();
        unsigned int v = atomicAdd(&d_count, 1u);
        s_flag = (v == NCTA - 1) ? 1u : 0u;
    }
    __syncthreads();
    if (s_flag) {
        __threadfence();   // acquire: make all CTAs' d_partial visible
        if (tid < NB*NO) {
            float s = 0.f;
            for (int i = 0; i < 64; i++) s += d_partial[tid*64 + i];
            float m = s * (1.0f / (float)NPIX);
            s_vals[tid] = m;
            if (1 + tid < out_size) out[1 + tid] = m;
        }
        __syncthreads();
        if (tid == 0) {
            float s = 0.f;
            #pragma unroll
            for (int i = 0; i < NB*NO; i++) s += s_vals[i];
            if (out_size > 0) out[0] = s / (float)(NB*NO);
            d_count = 0;   // reset for next replay
        }
    }
}

extern "C" void kernel_launch(void* const* d_in, const int* in_sizes, int n_in,
                              void* d_out, int out_size) {
    const float* outs = (const float*)d_in[0];
    const float* labs = (const float*)d_in[1];
    if (n_in >= 2 && in_sizes[0] < in_sizes[1]) {  // defensive: outputs is larger
        const float* tmp = outs; outs = labs; labs = tmp;
    }

    const int SMEM = SMEM_FLOATS * (int)sizeof(float);   // 193,120 B
    cudaFuncSetAttribute(fused_kernel, cudaFuncAttributeMaxDynamicSharedMemorySize, SMEM);
    fused_kernel<<<dim3(8, 8, NB), NT, SMEM>>>(outs, labs, (float*)d_out, out_size);
}

// round 5
// speedup vs baseline: 2.4109x; 1.2495x over previous
#include <cuda_runtime.h>
#include <math.h>

#define IMG   512
#define NPIX  (IMG*IMG)
#define NB    4
#define NO    6
#define NL    4
#define TILE  64
#define TS    71      // bc/ac extent+stride (odd -> conflict-free)
#define XR    78      // raw tile rows/cols (double halo)
#define XS2   79      // raw tile stride (odd)
#define HS    65      // H box-buffer stride (odd), 71 rows x 64 cols used
#define EPS   1e-20f
#define NT    1024
#define NCTA  (8*8*NB)   // 256

// sizes in floats
#define SZ_BC   (TS*TS)        // 5041
#define SZ_X    (XR*XS2)       // 6162
#define SZ_HM   (XR*TS)        // 5538
#define SZ_HB   (TS*HS)        // 4615 (one box buffer)
#define R_FLOATS (5*SZ_HB)     // 23075 >= SZ_X+SZ_HM (11700)
#define SMEM_FLOATS (NL*SZ_BC + SZ_BC + R_FLOATS)   // 48280 -> 193,120 B

__device__ float d_partial[NB*NO*64];
__device__ unsigned int d_count = 0;

// ---- load raw 78x78 tile (zero outside image) ----
__device__ __forceinline__ void load_tile(const float* __restrict__ src, float* __restrict__ X,
                                          int tx0, int ty0, int tid) {
    for (int idx = tid; idx < XR*XR; idx += NT) {
        int r = idx / XR, c = idx % XR;
        int gr = ty0 + r - 6, gc = tx0 + c - 6;
        float v = 0.f;
        if ((unsigned)gr < (unsigned)IMG && (unsigned)gc < (unsigned)IMG)
            v = __ldg(src + gr*IMG + gc);
        X[r*XS2 + c] = v;
    }
}

// ---- Hm[r][c] = sum_{d=0..7} X[r][c+d], r<78, c<71 (reg-staged) ----
__device__ __forceinline__ void hmean(const float* __restrict__ X, float* __restrict__ Hm, int tid) {
    for (int idx = tid; idx < XR*8; idx += NT) {
        int r = idx % XR, q = idx / XR;
        int c0 = q * 9;
        int cnt = (q == 7) ? 8 : 9;
        const float* xr = X + r*XS2 + c0;
        float w[16];
        #pragma unroll
        for (int d = 0; d < 16; d++) w[d] = xr[d];         // col <= 78 < stride 79
        float s = w[0]+w[1]+w[2]+w[3]+w[4]+w[5]+w[6]+w[7];
        float* hr = Hm + r*TS + c0;
        hr[0] = s;
        #pragma unroll
        for (int k = 1; k < 9; k++)
            if (k < cnt) { s += w[k+7] - w[k-1]; hr[k] = s; }
    }
}

// ---- OUT[r][c] = inside ? X[r+3][c+3] - boxmean : 0, r,c<71 ----
__device__ __forceinline__ void centered(const float* __restrict__ X, const float* __restrict__ Hm,
                                         float* __restrict__ OUT, int tx0, int ty0, int tid) {
    for (int idx = tid; idx < TS*8; idx += NT) {
        int c = idx % TS, q = idx / TS;
        int r0 = q * 9;
        int cnt = (q == 7) ? 8 : 9;
        float h[16];
        #pragma unroll
        for (int d = 0; d < 16; d++) h[d] = Hm[min(r0 + d, 77)*TS + c];
        float xv[9];
        #pragma unroll
        for (int k = 0; k < 9; k++) xv[k] = X[(r0 + k + 3)*XS2 + (c + 3)];
        float s = h[0]+h[1]+h[2]+h[3]+h[4]+h[5]+h[6]+h[7];
        int gc = tx0 + c - 3;
        bool cin = (unsigned)gc < (unsigned)IMG;
        #pragma unroll
        for (int k = 0; k < 9; k++) {
            if (k < cnt) {
                int r = r0 + k;
                int gr = ty0 + r - 3;
                float v = 0.f;
                if (cin && (unsigned)gr < (unsigned)IMG) v = xv[k] - s * (1.f/64.f);
                OUT[r*TS + c] = v;
                if (k + 1 < cnt) s += h[k+8] - h[k];
            }
        }
    }
}

// ---- 4 vertical window sums of Hb at column cl, row group g (rows g*4..g*4+3) ----
__device__ __forceinline__ void vsum4(const float* __restrict__ Hb, int g, int cl, float* out) {
    float ps[12];
    ps[0] = 0.f;
    #pragma unroll
    for (int k = 0; k < 11; k++) ps[k+1] = ps[k] + Hb[(g*4 + k)*HS + cl];
    #pragma unroll
    for (int k = 0; k < 4; k++) out[k] = ps[k+8] - ps[k];
}

// =========================================================================
// fused: one CTA per (batch, 64x64 tile), 1024 threads, finalize in-kernel.
// =========================================================================
__global__ void __launch_bounds__(NT, 1)
fused_kernel(const float* __restrict__ outs, const float* __restrict__ labs,
             float* __restrict__ out, int out_size) {
    extern __shared__ float sm[];
    float* BC = sm;                  // NL * 5041
    float* AC = BC + NL*SZ_BC;       // 5041 (head doubles as reduction scratch)
    float* R  = AC + SZ_BC;          // 23075: prep {X, Hm} / corr {H0..H4}
    float* X  = R;                   // 6162, stride 79
    float* Hm = R + SZ_X;            // 5538, stride 71
    __shared__ unsigned int s_flag;
    __shared__ float s_vals[NB*NO];

    int tx0 = blockIdx.x * TILE, ty0 = blockIdx.y * TILE;
    int b = blockIdx.z;
    int tid = threadIdx.x;
    int cl = tid & 63, g = tid >> 6;      // pixel column / row-group (g in 0..15, 4 rows)
    int lane = tid & 31, wid = tid >> 5;

    // ---------------- phase 1: labels -> BC[l], rsjj regs ----------------
    for (int l = 0; l < NL; l++) {
        load_tile(labs + (size_t)(b*NL + l)*NPIX, X, tx0, ty0, tid);
        __syncthreads();
        hmean(X, Hm, tid);
        __syncthreads();
        centered(X, Hm, BC + l*SZ_BC, tx0, ty0, tid);
        __syncthreads();   // BC[l] ready; X/Hm retire before next load / hprod
    }

    // one phase: box-row sums of bc_l^2 for all 4 labels -> R[0..3]
    for (int idx = tid; idx < TS*8; idx += NT) {
        int r = idx % TS, q = idx / TS;
        int c0 = q * 8;
        #pragma unroll
        for (int l = 0; l < NL; l++) {
            const float* br = BC + l*SZ_BC + r*TS + c0;
            float w[15];
            #pragma unroll
            for (int d = 0; d < 15; d++) { float v = br[d]; w[d] = v*v; }
            float s = w[0]+w[1]+w[2]+w[3]+w[4]+w[5]+w[6]+w[7];
            float* hr = R + l*SZ_HB + r*HS + c0;
            hr[0] = s;
            #pragma unroll
            for (int k = 1; k < 8; k++) { s += w[k+7] - w[k-1]; hr[k] = s; }
        }
    }
    __syncthreads();

    float rsjjR[NL][4];
    #pragma unroll
    for (int l = 0; l < NL; l++) {
        float v4[4];
        vsum4(R + l*SZ_HB, g, cl, v4);
        #pragma unroll
        for (int k = 0; k < 4; k++) rsjjR[l][k] = rsqrtf(fmaxf(v4[k], EPS));
    }
    __syncthreads();   // rsjj in regs; R region free for phase 2

    // ---------------- phase 2: outputs ----------------
    for (int o = 0; o < NO; o++) {
        load_tile(outs + (size_t)(b*NO + o)*NPIX, X, tx0, ty0, tid);
        __syncthreads();
        hmean(X, Hm, tid);
        __syncthreads();
        centered(X, Hm, AC, tx0, ty0, tid);
        __syncthreads();   // AC ready; X/Hm dead -> R hosts H0..H4

        // one phase: ac loaded once; j=0 -> ac*ac, j=1..4 -> ac*bc_{j-1}
        for (int idx = tid; idx < TS*8; idx += NT) {
            int r = idx % TS, q = idx / TS;
            int c0 = q * 8;
            const float* ar = AC + r*TS + c0;
            float a[15];
            #pragma unroll
            for (int d = 0; d < 15; d++) a[d] = ar[d];
            {   // sii rows
                float w[15];
                #pragma unroll
                for (int d = 0; d < 15; d++) w[d] = a[d]*a[d];
                float s = w[0]+w[1]+w[2]+w[3]+w[4]+w[5]+w[6]+w[7];
                float* hr = R + r*HS + c0;
                hr[0] = s;
                #pragma unroll
                for (int k = 1; k < 8; k++) { s += w[k+7] - w[k-1]; hr[k] = s; }
            }
            #pragma unroll
            for (int l = 0; l < NL; l++) {
                const float* br = BC + l*SZ_BC + r*TS + c0;
                float w[15];
                #pragma unroll
                for (int d = 0; d < 15; d++) w[d] = a[d]*br[d];
                float s = w[0]+w[1]+w[2]+w[3]+w[4]+w[5]+w[6]+w[7];
                float* hr = R + (l+1)*SZ_HB + r*HS + c0;
                hr[0] = s;
                #pragma unroll
                for (int k = 1; k < 8; k++) { s += w[k+7] - w[k-1]; hr[k] = s; }
            }
        }
        __syncthreads();

        float rsii[4];
        {
            float v4[4];
            vsum4(R, g, cl, v4);
            #pragma unroll
            for (int k = 0; k < 4; k++) rsii[k] = rsqrtf(fmaxf(v4[k], EPS));
        }

        float maxcc[4];
        #pragma unroll
        for (int k = 0; k < 4; k++) maxcc[k] = -1.0f;

        #pragma unroll
        for (int l = 0; l < NL; l++) {
            float sij4[4];
            vsum4(R + (l+1)*SZ_HB, g, cl, sij4);
            #pragma unroll
            for (int k = 0; k < 4; k++) {
                float cc = sij4[k] * (rsii[k] * rsjjR[l][k]);
                maxcc[k] = fmaxf(maxcc[k], cc);
            }
        }

        float local = 0.f;
        #pragma unroll
        for (int k = 0; k < 4; k++) local += 1.0f - fminf(1.0f, maxcc[k]);
        #pragma unroll
        for (int off = 16; off > 0; off >>= 1)
            local += __shfl_down_sync(0xFFFFFFFFu, local, off);
        if (lane == 0) AC[wid] = local;   // AC readers (hprod) retired at last sync
        __syncthreads();
        if (tid == 0) {
            float s = 0.f;
            #pragma unroll
            for (int w2 = 0; w2 < 32; w2++) s += AC[w2];
            d_partial[(b*NO + o)*64 + blockIdx.y*8 + blockIdx.x] = s;
        }
        // next load_tile writes R (disjoint from AC scratch); tid0 rejoins at
        // the post-load barrier before the next centered overwrites AC.
    }

    // ---------------- in-kernel finalize (last CTA, fixed-order sums) ------
    if (tid == 0) {
        __threadfence();
        unsigned int v = atomicAdd(&d_count, 1u);
        s_flag = (v == NCTA - 1) ? 1u : 0u;
    }
    __syncthreads();
    if (s_flag) {
        __threadfence();   // acquire: all CTAs' d_partial visible
        if (tid < NB*NO) {
            float s = 0.f;
            for (int i = 0; i < 64; i++) s += d_partial[tid*64 + i];
            float m = s * (1.0f / (float)NPIX);
            s_vals[tid] = m;
            if (1 + tid < out_size) out[1 + tid] = m;
        }
        __syncthreads();
        if (tid == 0) {
            float s = 0.f;
            #pragma unroll
            for (int i = 0; i < NB*NO; i++) s += s_vals[i];
            if (out_size > 0) out[0] = s / (float)(NB*NO);
            d_count = 0;   // reset for next replay
        }
    }
}

extern "C" void kernel_launch(void* const* d_in, const int* in_sizes, int n_in,
                              void* d_out, int out_size) {
    const float* outs = (const float*)d_in[0];
    const float* labs = (const float*)d_in[1];
    if (n_in >= 2 && in_sizes[0] < in_sizes[1]) {  // defensive: outputs is larger
        const float* tmp = outs; outs = labs; labs = tmp;
    }

    const int SMEM = SMEM_FLOATS * (int)sizeof(float);   // 193,120 B
    cudaFuncSetAttribute(fused_kernel, cudaFuncAttributeMaxDynamicSharedMemorySize, SMEM);
    fused_kernel<<<dim3(8, 8, NB), NT, SMEM>>>(outs, labs, (float*)d_out, out_size);
}